// round 8
// baseline (speedup 1.0000x reference)
#include <cuda_runtime.h>

// SequentialConv: B=8, C=64, H=192, W=256, 3x3, sequential row recurrence.
// Persistent wavefront: 8 batches x 16 width-tiles = 128 CTAs (all resident).
// Round 8: 512 threads (4 warps/SMSP) for latency coverage; 1 co x 2 cols per
// thread; per-(ci,co) 12-float weight records (2xLDS.128 + 1 scalar);
// R7's 2-barrier/step sync structure kept verbatim.

#define Bb 8
#define Cc 64
#define Hh 192
#define Ww 256
#define NT 16
#define TW 16
#define NTHR 512
#define RST 20          // smem row stride in floats (18 used: w0-1 .. w0+16)
#define WREC 12         // padded weight record per (ci,co): 9 used + 3 pad (48 B)

#define WSM_FLOATS (Cc * Cc * WREC)     // [ci][co][WREC] = 196608 B
#define RBUF_FLOATS (5 * Cc * RST)      // U0,U1,U2 ring + O0,O1 pingpong
#define SMEM_BYTES ((WSM_FLOATS + RBUF_FLOATS) * 4)

__device__ int g_flags[Bb * NT];

__global__ void sc_init_flags() {
    int i = threadIdx.x;
    if (i < Bb * NT) g_flags[i] = 0;
}

__global__ void __launch_bounds__(NTHR, 1) sc_main(
    const float* __restrict__ X, const float* __restrict__ Wt,
    const float* __restrict__ Bs, float* __restrict__ Out)
{
    extern __shared__ float smem[];
    float* wsm  = smem;                       // [(ci*64+co)*WREC + kh*3+kw]
    float* ubuf = smem + WSM_FLOATS;          // U0..U2: updated-row ring
    float* obuf = ubuf + 3 * Cc * RST;        // O0,O1: orig-row pingpong

    const int tile = blockIdx.x;
    const int b    = blockIdx.y;
    const int w0   = tile * TW;
    const int tid  = threadIdx.x;

    // Weights: one 9-used-float record per (ci,co), stride WREC (16B-aligned).
    for (int i = tid; i < Cc * Cc * 9; i += NTHR) {
        int j = i % 9; int r = i / 9;
        int co = r & 63; int ci = r >> 6;
        int kh = j / 3, kw = j % 3;
        wsm[r * WREC + j] = Wt[((co * Cc + ci) * 3 + kh) * 3 + kw];
    }

    const float* Xb = X   + (size_t)b * Cc * Hh * Ww;
    float*       Ob = Out + (size_t)b * Cc * Hh * Ww;

    // Rows 0,1 (unchanged) -> U0,U1 with halo; copy to Out. Zero U2 halo cols.
    for (int r = 0; r < 2; r++) {
        for (int i = tid; i < Cc * 18; i += NTHR) {
            int ci = i / 18, wi = i % 18; int w = w0 - 1 + wi;
            float v = (w >= 0 && w < Ww) ? Xb[(ci * Hh + r) * Ww + w] : 0.f;
            ubuf[(r * Cc + ci) * RST + wi] = v;
        }
        for (int i = tid; i < Cc * TW; i += NTHR) {
            int ci = i / TW, wq = i % TW;
            Ob[(ci * Hh + r) * Ww + w0 + wq] = Xb[(ci * Hh + r) * Ww + w0 + wq];
        }
    }
    if (tid < Cc) {
        ubuf[(2 * Cc + tid) * RST + 0]  = 0.f;
        ubuf[(2 * Cc + tid) * RST + 17] = 0.f;
    }

    // Thread -> (1 output channel co, 2 output columns at wl2)
    const int co  = tid >> 3;            // 0..63
    const int wl2 = (tid & 7) * 2;       // 0..14, even
    const float bb = __ldg(&Bs[co]);

    int* myflag = &g_flags[b * NT + tile];
    int* lflag  = (tile > 0)      ? &g_flags[b * NT + tile - 1] : (int*)0;
    int* rflag  = (tile < NT - 1) ? &g_flags[b * NT + tile + 1] : (int*)0;

    // Publish rows 0,1 (flag=1) only after they are globally visible.
    __threadfence();
    __syncthreads();
    if (tid == 0) atomicExch(myflag, 1);

    // Prefetch orig row 2 into registers (3 elems/thread covers 64*18=1152).
    float pv[3];
    #pragma unroll
    for (int k = 0; k < 3; k++) {
        int idx = tid + k * NTHR;
        if (idx < Cc * 18) {
            int ci = idx / 18, wi = idx % 18; int w = w0 - 1 + wi;
            pv[k] = (w >= 0 && w < Ww) ? __ldg(&Xb[(ci * Hh + 2) * Ww + w]) : 0.f;
        }
    }

    for (int pos = 2; pos < Hh; pos++) {
        float*       sU2 = ubuf + (pos % 3) * Cc * RST;        // write: row pos
        const float* sU0 = ubuf + ((pos + 1) % 3) * Cc * RST;  // row pos-2
        float*       sU1 = ubuf + ((pos + 2) % 3) * Cc * RST;  // row pos-1 (halo lands here)
        float*       sO  = obuf + (pos & 1) * Cc * RST;        // orig row pos

        // Store prefetched orig row pos.
        #pragma unroll
        for (int k = 0; k < 3; k++) {
            int idx = tid + k * NTHR;
            if (idx < Cc * 18) {
                int ci = idx / 18, wi = idx % 18;
                sO[ci * RST + wi] = pv[k];
            }
        }
        // Halo acquire for row pos-1 into sU1 cols 0/17 (overlaps STS above).
        if (tid < Cc) {
            if (lflag) {
                while (*(volatile int*)lflag < pos - 1) __nanosleep(32);
                __threadfence();
                sU1[tid * RST + 0] = __ldcg(&Ob[((size_t)tid * Hh + pos - 1) * Ww + w0 - 1]);
            }
        } else if (tid >= NTHR - Cc) {
            int ci = tid - (NTHR - Cc);
            if (rflag) {
                while (*(volatile int*)rflag < pos - 1) __nanosleep(32);
                __threadfence();
                sU1[ci * RST + 17] = __ldcg(&Ob[((size_t)ci * Hh + pos - 1) * Ww + w0 + TW]);
            }
        }
        __syncthreads();   // orig row + fresh halo visible

        float a0 = 0.f, a1 = 0.f;
        const float* i0 = sU0 + wl2;
        const float* i1 = sU1 + wl2;
        const float* i2 = sO  + wl2;
        const float* wb = wsm + co * WREC;

        #pragma unroll 4
        for (int ci = 0; ci < Cc; ci++) {
            const float4* wv = (const float4*)(wb + ci * (Cc * WREC));
            float4 wA = wv[0];                         // w00 w01 w02 w10
            float4 wB = wv[1];                         // w11 w12 w20 w21
            float  w8 = *((const float*)(wv) + 8);     // w22

            float2 pA = *(const float2*)(i0 + ci * RST);
            float2 pB = *(const float2*)(i0 + ci * RST + 2);
            a0 += pA.x * wA.x; a1 += pA.y * wA.x;
            a0 += pA.y * wA.y; a1 += pB.x * wA.y;
            a0 += pB.x * wA.z; a1 += pB.y * wA.z;

            pA = *(const float2*)(i1 + ci * RST);
            pB = *(const float2*)(i1 + ci * RST + 2);
            a0 += pA.x * wA.w; a1 += pA.y * wA.w;
            a0 += pA.y * wB.x; a1 += pB.x * wB.x;
            a0 += pB.x * wB.y; a1 += pB.y * wB.y;

            pA = *(const float2*)(i2 + ci * RST);
            pB = *(const float2*)(i2 + ci * RST + 2);
            a0 += pA.x * wB.z; a1 += pA.y * wB.z;
            a0 += pA.y * wB.w; a1 += pB.x * wB.w;
            a0 += pB.x * w8;   a1 += pB.y * w8;
        }

        // res = orig + tanh(y + bias); orig from separate slot -> no WAR barrier.
        const float* o0 = sO + co * RST + wl2 + 1;
        float r0 = o0[0] + tanhf(a0 + bb);
        float r1 = o0[1] + tanhf(a1 + bb);

        // Write row pos: smem interior (slot held dead row pos-3) + Out.
        float* wr = sU2 + co * RST + wl2 + 1;
        wr[0] = r0; wr[1] = r1;
        *(float2*)(Ob + ((size_t)co * Hh + pos) * Ww + w0 + wl2) = make_float2(r0, r1);

        // Prefetch next orig row (overlaps fence/barrier).
        if (pos + 1 < Hh) {
            #pragma unroll
            for (int k = 0; k < 3; k++) {
                int idx = tid + k * NTHR;
                if (idx < Cc * 18) {
                    int ci = idx / 18, wi = idx % 18; int w = w0 - 1 + wi;
                    pv[k] = (w >= 0 && w < Ww) ? __ldg(&Xb[(ci * Hh + pos + 1) * Ww + w]) : 0.f;
                }
            }
        }

        __threadfence();
        __syncthreads();
        if (tid == 0) atomicExch(myflag, pos);
    }
}

extern "C" void kernel_launch(void* const* d_in, const int* in_sizes, int n_in,
                              void* d_out, int out_size) {
    const float* X  = (const float*)d_in[0];
    const float* Wt = (const float*)d_in[1];
    const float* Bs = (const float*)d_in[2];
    float* Out = (float*)d_out;
    (void)in_sizes; (void)n_in; (void)out_size;

    cudaFuncSetAttribute(sc_main, cudaFuncAttributeMaxDynamicSharedMemorySize, SMEM_BYTES);

    sc_init_flags<<<1, 128>>>();
    sc_main<<<dim3(NT, Bb), NTHR, SMEM_BYTES>>>(X, Wt, Bs, Out);
}

// round 9
// speedup vs baseline: 2.4184x; 2.4184x over previous
#include <cuda_runtime.h>
#include <cuda_bf16.h>

// SequentialConv: B=8, C=64, H=192, W=256, 3x3, sequential row recurrence.
// Persistent wavefront: 8 batches x 16 width-tiles = 128 CTAs (all resident).
// Round 9: tensor-core path. Per step, D[64co,16w] = W[64, 576] * Im[576, 16]
// via mma.sync.m16n8k16 bf16 with hi/lo split precision (3 accumulating MMAs:
// hi*hi + hi*lo + lo*hi). Weights pre-packed into exact fragment layout
// (1 LDS.128 per A frag). Rows stored [w][ci] bf16 (stride 72: conflict-free
// B frags). kw = row-offset addressing, kh = ring slot. R7 sync kept.

#define Bb 8
#define Cc 64
#define Hh 192
#define Ww 256
#define NT 16
#define TW 16
#define NTHR 256
#define CIST 72                      // ci stride in row slots (bank-conflict-free)
#define SLOT_ELEMS (18 * CIST)       // bf16 per array per slot

#define AF_U32 36864                 // 4mi * 9khkw * 2hl * 4q * 32lane * 4reg
#define AF_BYTES (AF_U32 * 4)        // 147456
#define BARR_BYTES (5 * SLOT_ELEMS * 2)      // 12960 per array (hi / lo)
#define OF_FLOATS (2 * Cc * 16)              // orig-row f32 pingpong (interior)
#define SMEM_BYTES (AF_BYTES + 2 * BARR_BYTES + OF_FLOATS * 4)

typedef unsigned int u32;

__device__ int g_flags[Bb * NT];

__global__ void sc_init_flags() {
    int i = threadIdx.x;
    if (i < Bb * NT) g_flags[i] = 0;
}

__device__ __forceinline__ void split_sts(__nv_bfloat16* ph, __nv_bfloat16* pl, float v) {
    __nv_bfloat16 h = __float2bfloat16(v);
    *ph = h;
    *pl = __float2bfloat16(v - __bfloat162float(h));
}

__device__ __forceinline__ void mma16816(float& d0, float& d1, float& d2, float& d3,
                                         u32 a0, u32 a1, u32 a2, u32 a3,
                                         u32 b0, u32 b1) {
    asm("mma.sync.aligned.m16n8k16.row.col.f32.bf16.bf16.f32 "
        "{%0,%1,%2,%3},{%4,%5,%6,%7},{%8,%9},{%0,%1,%2,%3};"
        : "+f"(d0), "+f"(d1), "+f"(d2), "+f"(d3)
        : "r"(a0), "r"(a1), "r"(a2), "r"(a3), "r"(b0), "r"(b1));
}

__global__ void __launch_bounds__(NTHR, 1) sc_main(
    const float* __restrict__ X, const float* __restrict__ Wt,
    const float* __restrict__ Bs, float* __restrict__ Out)
{
    extern __shared__ char smem[];
    u32*            AFu = (u32*)smem;                         // A fragments
    const uint4*    AF4 = (const uint4*)smem;
    __nv_bfloat16*  BHI = (__nv_bfloat16*)(smem + AF_BYTES);  // 5 slots [w][ci]
    __nv_bfloat16*  BLO = BHI + 5 * SLOT_ELEMS;
    float*          OF  = (float*)(BLO + 5 * SLOT_ELEMS);     // [2][64][16] f32

    const int tile = blockIdx.x;
    const int b    = blockIdx.y;
    const int w0   = tile * TW;
    const int tid  = threadIdx.x;
    const int wid  = tid >> 5;
    const int lane = tid & 31;
    const int g    = lane >> 2;
    const int tg   = lane & 3;
    const int mi   = wid >> 1;           // co-tile 0..3
    const int ni   = wid & 1;            // w-tile 0..1

    // ---- Init A fragments: exact m16n8k16 A layout, hi/lo split. ----
    // reg r: 0:[co=g, ci=base] 1:[co=g+8, base] 2:[g, base+8] 3:[g+8, base+8]
    for (int i = tid; i < AF_U32; i += NTHR) {
        int r = i & 3; int ln = (i >> 2) & 31; int q = (i >> 7) & 3;
        int hl = (i >> 9) & 1; int t = i >> 10; int khkw = t % 9; int mI = t / 9;
        int gg = ln >> 2, tt = ln & 3;
        int co = mI * 16 + gg + ((r & 1) ? 8 : 0);
        int ci = q * 16 + 2 * tt + ((r & 2) ? 8 : 0);
        int kh = khkw / 3, kw = khkw % 3;
        float f0 = Wt[((co * Cc + ci) * 3 + kh) * 3 + kw];
        float f1 = Wt[((co * Cc + ci + 1) * 3 + kh) * 3 + kw];
        __nv_bfloat16 v0, v1;
        if (hl == 0) { v0 = __float2bfloat16(f0); v1 = __float2bfloat16(f1); }
        else {
            __nv_bfloat16 h0 = __float2bfloat16(f0), h1 = __float2bfloat16(f1);
            v0 = __float2bfloat16(f0 - __bfloat162float(h0));
            v1 = __float2bfloat16(f1 - __bfloat162float(h1));
        }
        AFu[i] = (u32)__bfloat16_as_ushort(v0) | ((u32)__bfloat16_as_ushort(v1) << 16);
    }

    const float* Xb = X   + (size_t)b * Cc * Hh * Ww;
    float*       Ob = Out + (size_t)b * Cc * Hh * Ww;

    // ---- Rows 0,1 (unchanged) -> slots 0,1 (bf16 split, incl halo); Out copy. ----
    for (int r = 0; r < 2; r++) {
        for (int i = tid; i < Cc * 18; i += NTHR) {
            int ci = i / 18, wi = i % 18; int w = w0 - 1 + wi;
            float v = (w >= 0 && w < Ww) ? Xb[(ci * Hh + r) * Ww + w] : 0.f;
            split_sts(&BHI[r * SLOT_ELEMS + wi * CIST + ci],
                      &BLO[r * SLOT_ELEMS + wi * CIST + ci], v);
        }
        for (int i = tid; i < Cc * TW; i += NTHR) {
            int ci = i / TW, wq = i % TW;
            Ob[(ci * Hh + r) * Ww + w0 + wq] = Xb[(ci * Hh + r) * Ww + w0 + wq];
        }
    }
    // Zero slot 2 halo cols (edge tiles keep all upd-slot halos 0 forever).
    if (tid < Cc) {
        BHI[2 * SLOT_ELEMS + tid] = __float2bfloat16(0.f);
        BLO[2 * SLOT_ELEMS + tid] = __float2bfloat16(0.f);
        BHI[2 * SLOT_ELEMS + 17 * CIST + tid] = __float2bfloat16(0.f);
        BLO[2 * SLOT_ELEMS + 17 * CIST + tid] = __float2bfloat16(0.f);
    }

    const float bs0 = __ldg(&Bs[mi * 16 + g]);
    const float bs1 = __ldg(&Bs[mi * 16 + g + 8]);

    int* myflag = &g_flags[b * NT + tile];
    int* lflag  = (tile > 0)      ? &g_flags[b * NT + tile - 1] : (int*)0;
    int* rflag  = (tile < NT - 1) ? &g_flags[b * NT + tile + 1] : (int*)0;

    __threadfence();
    __syncthreads();
    if (tid == 0) atomicExch(myflag, 1);   // rows 0,1 published

    // Prefetch orig row 2.
    float pv[5];
    #pragma unroll
    for (int k = 0; k < 5; k++) {
        int idx = tid + k * NTHR;
        if (idx < Cc * 18) {
            int ci = idx / 18, wi = idx % 18; int w = w0 - 1 + wi;
            pv[k] = (w >= 0 && w < Ww) ? __ldg(&Xb[(ci * Hh + 2) * Ww + w]) : 0.f;
        }
    }

    for (int pos = 2; pos < Hh; pos++) {
        const int OS = 3 + (pos & 1);            // orig slot (pingpong)
        const int US = pos % 3;                  // write slot for updated row pos
        const int S0 = (pos + 1) % 3;            // updated row pos-2
        const int S1 = (pos + 2) % 3;            // updated row pos-1

        // Stage orig row pos: bf16 split (full 18 cols) + f32 interior.
        #pragma unroll
        for (int k = 0; k < 5; k++) {
            int idx = tid + k * NTHR;
            if (idx < Cc * 18) {
                int ci = idx / 18, wi = idx % 18;
                split_sts(&BHI[OS * SLOT_ELEMS + wi * CIST + ci],
                          &BLO[OS * SLOT_ELEMS + wi * CIST + ci], pv[k]);
                if (wi >= 1 && wi <= 16)
                    OF[(pos & 1) * Cc * 16 + ci * 16 + (wi - 1)] = pv[k];
            }
        }
        // Halo acquire for updated row pos-1 into slot S1 cols 0/17.
        if (tid < Cc) {
            if (lflag) {
                while (*(volatile int*)lflag < pos - 1) __nanosleep(32);
                __threadfence();
                float v = __ldcg(&Ob[((size_t)tid * Hh + pos - 1) * Ww + w0 - 1]);
                split_sts(&BHI[S1 * SLOT_ELEMS + tid], &BLO[S1 * SLOT_ELEMS + tid], v);
            }
        } else if (tid >= NTHR - Cc) {
            int ci = tid - (NTHR - Cc);
            if (rflag) {
                while (*(volatile int*)rflag < pos - 1) __nanosleep(32);
                __threadfence();
                float v = __ldcg(&Ob[((size_t)ci * Hh + pos - 1) * Ww + w0 + TW]);
                split_sts(&BHI[S1 * SLOT_ELEMS + 17 * CIST + ci],
                          &BLO[S1 * SLOT_ELEMS + 17 * CIST + ci], v);
            }
        }
        __syncthreads();

        // ---- Tensor compute: D[16co x 8w] per warp. ----
        float d0 = 0.f, d1 = 0.f, d2 = 0.f, d3 = 0.f;
        const int slot_of[3] = {S0, S1, OS};
        #pragma unroll
        for (int kh = 0; kh < 3; kh++) {
            const __nv_bfloat16* bh =
                BHI + slot_of[kh] * SLOT_ELEMS + (ni * 8 + g) * CIST + 2 * tg;
            const __nv_bfloat16* bl =
                BLO + slot_of[kh] * SLOT_ELEMS + (ni * 8 + g) * CIST + 2 * tg;
            #pragma unroll
            for (int kw = 0; kw < 3; kw++) {
                const int khkw = kh * 3 + kw;
                const __nv_bfloat16* bhk = bh + kw * CIST;
                const __nv_bfloat16* blk = bl + kw * CIST;
                #pragma unroll
                for (int q = 0; q < 4; q++) {
                    uint4 ah = AF4[((((mi * 9 + khkw) * 2 + 0) * 4 + q) * 32) + lane];
                    uint4 al = AF4[((((mi * 9 + khkw) * 2 + 1) * 4 + q) * 32) + lane];
                    u32 b0h = *(const u32*)(bhk + q * 16);
                    u32 b1h = *(const u32*)(bhk + q * 16 + 8);
                    u32 b0l = *(const u32*)(blk + q * 16);
                    u32 b1l = *(const u32*)(blk + q * 16 + 8);
                    mma16816(d0, d1, d2, d3, ah.x, ah.y, ah.z, ah.w, b0h, b1h);
                    mma16816(d0, d1, d2, d3, ah.x, ah.y, ah.z, ah.w, b0l, b1l);
                    mma16816(d0, d1, d2, d3, al.x, al.y, al.z, al.w, b0h, b1h);
                }
            }
        }

        // ---- Epilogue: r = orig + tanh(d + bias). ----
        const int co0 = mi * 16 + g;
        const int wq  = ni * 8 + 2 * tg;     // even
        const float* ofp = OF + (pos & 1) * Cc * 16;
        float r00 = ofp[co0 * 16 + wq]       + tanhf(d0 + bs0);
        float r01 = ofp[co0 * 16 + wq + 1]   + tanhf(d1 + bs0);
        float r10 = ofp[(co0 + 8) * 16 + wq]     + tanhf(d2 + bs1);
        float r11 = ofp[(co0 + 8) * 16 + wq + 1] + tanhf(d3 + bs1);

        float* og = Ob + ((size_t)co0 * Hh + pos) * Ww + w0 + wq;
        *(float2*)og = make_float2(r00, r01);
        *(float2*)(og + 8 * (size_t)Hh * Ww) = make_float2(r10, r11);

        // Updated row -> slot US (interior cols wq+1, wq+2), bf16 split.
        __nv_bfloat16* uh = BHI + US * SLOT_ELEMS;
        __nv_bfloat16* ul = BLO + US * SLOT_ELEMS;
        split_sts(&uh[(wq + 1) * CIST + co0],     &ul[(wq + 1) * CIST + co0],     r00);
        split_sts(&uh[(wq + 2) * CIST + co0],     &ul[(wq + 2) * CIST + co0],     r01);
        split_sts(&uh[(wq + 1) * CIST + co0 + 8], &ul[(wq + 1) * CIST + co0 + 8], r10);
        split_sts(&uh[(wq + 2) * CIST + co0 + 8], &ul[(wq + 2) * CIST + co0 + 8], r11);

        // Prefetch next orig row (overlaps fence/barrier).
        if (pos + 1 < Hh) {
            #pragma unroll
            for (int k = 0; k < 5; k++) {
                int idx = tid + k * NTHR;
                if (idx < Cc * 18) {
                    int ci = idx / 18, wi = idx % 18; int w = w0 - 1 + wi;
                    pv[k] = (w >= 0 && w < Ww) ? __ldg(&Xb[(ci * Hh + pos + 1) * Ww + w]) : 0.f;
                }
            }
        }

        __threadfence();
        __syncthreads();
        if (tid == 0) atomicExch(myflag, pos);
    }
}

extern "C" void kernel_launch(void* const* d_in, const int* in_sizes, int n_in,
                              void* d_out, int out_size) {
    const float* X  = (const float*)d_in[0];
    const float* Wt = (const float*)d_in[1];
    const float* Bs = (const float*)d_in[2];
    float* Out = (float*)d_out;
    (void)in_sizes; (void)n_in; (void)out_size;

    cudaFuncSetAttribute(sc_main, cudaFuncAttributeMaxDynamicSharedMemorySize, SMEM_BYTES);

    sc_init_flags<<<1, 128>>>();
    sc_main<<<dim3(NT, Bb), NTHR, SMEM_BYTES>>>(X, Wt, Bs, Out);
}

// round 10
// speedup vs baseline: 2.6786x; 1.1076x over previous
#include <cuda_runtime.h>
#include <cuda_bf16.h>

// SequentialConv: B=8, C=64, H=192, W=256, 3x3, sequential row recurrence.
// Persistent wavefront: 8 batches x 16 width-tiles = 128 CTAs (all resident).
// Round 10: R9 tensor path + (1) per-kh accumulator sets (chain 108->36),
// (2) halo acquire overlapped with kh0/kh2 MMA (kh1 after mid-barrier),
// (3) prefetch hoisted after barrier1, tid0-only publish fence.

#define Bb 8
#define Cc 64
#define Hh 192
#define Ww 256
#define NT 16
#define TW 16
#define NTHR 256
#define CIST 72                      // ci stride in row slots (bank-conflict-free)
#define SLOT_ELEMS (18 * CIST)       // bf16 per array per slot

#define AF_U32 36864                 // 4mi * 9khkw * 2hl * 4q * 32lane * 4reg
#define AF_BYTES (AF_U32 * 4)        // 147456
#define BARR_BYTES (5 * SLOT_ELEMS * 2)      // per array (hi / lo)
#define OF_FLOATS (2 * Cc * 16)              // orig-row f32 pingpong (interior)
#define SMEM_BYTES (AF_BYTES + 2 * BARR_BYTES + OF_FLOATS * 4)

typedef unsigned int u32;

__device__ int g_flags[Bb * NT];

__global__ void sc_init_flags() {
    int i = threadIdx.x;
    if (i < Bb * NT) g_flags[i] = 0;
}

__device__ __forceinline__ void split_sts(__nv_bfloat16* ph, __nv_bfloat16* pl, float v) {
    __nv_bfloat16 h = __float2bfloat16(v);
    *ph = h;
    *pl = __float2bfloat16(v - __bfloat162float(h));
}

__device__ __forceinline__ void mma16816(float* d,
                                         u32 a0, u32 a1, u32 a2, u32 a3,
                                         u32 b0, u32 b1) {
    asm("mma.sync.aligned.m16n8k16.row.col.f32.bf16.bf16.f32 "
        "{%0,%1,%2,%3},{%4,%5,%6,%7},{%8,%9},{%0,%1,%2,%3};"
        : "+f"(d[0]), "+f"(d[1]), "+f"(d[2]), "+f"(d[3])
        : "r"(a0), "r"(a1), "r"(a2), "r"(a3), "r"(b0), "r"(b1));
}

// One kh plane: 3 kw x 4 q x 3 split-terms = 36 MMAs into dacc.
#define CONV_KH(dacc, SLOT, KH)                                               \
  {                                                                           \
    const __nv_bfloat16* bh_ = BHI + (SLOT) * SLOT_ELEMS + wrow;              \
    const __nv_bfloat16* bl_ = BLO + (SLOT) * SLOT_ELEMS + wrow;              \
    _Pragma("unroll")                                                         \
    for (int kw = 0; kw < 3; kw++) {                                          \
      const int khkw = (KH) * 3 + kw;                                         \
      const __nv_bfloat16* bhk = bh_ + kw * CIST;                             \
      const __nv_bfloat16* blk = bl_ + kw * CIST;                             \
      _Pragma("unroll")                                                       \
      for (int q = 0; q < 4; q++) {                                           \
        uint4 ah = AF4[(((mi * 9 + khkw) * 2 + 0) * 4 + q) * 32 + lane];      \
        uint4 al = AF4[(((mi * 9 + khkw) * 2 + 1) * 4 + q) * 32 + lane];      \
        u32 b0h = *(const u32*)(bhk + q * 16);                                \
        u32 b1h = *(const u32*)(bhk + q * 16 + 8);                            \
        u32 b0l = *(const u32*)(blk + q * 16);                                \
        u32 b1l = *(const u32*)(blk + q * 16 + 8);                            \
        mma16816(dacc, ah.x, ah.y, ah.z, ah.w, b0h, b1h);                     \
        mma16816(dacc, ah.x, ah.y, ah.z, ah.w, b0l, b1l);                     \
        mma16816(dacc, al.x, al.y, al.z, al.w, b0h, b1h);                     \
      }                                                                       \
    }                                                                         \
  }

__global__ void __launch_bounds__(NTHR, 1) sc_main(
    const float* __restrict__ X, const float* __restrict__ Wt,
    const float* __restrict__ Bs, float* __restrict__ Out)
{
    extern __shared__ char smem[];
    u32*            AFu = (u32*)smem;                         // A fragments
    const uint4*    AF4 = (const uint4*)smem;
    __nv_bfloat16*  BHI = (__nv_bfloat16*)(smem + AF_BYTES);  // 5 slots [w][ci]
    __nv_bfloat16*  BLO = BHI + 5 * SLOT_ELEMS;
    float*          OF  = (float*)(BLO + 5 * SLOT_ELEMS);     // [2][64][16] f32

    const int tile = blockIdx.x;
    const int b    = blockIdx.y;
    const int w0   = tile * TW;
    const int tid  = threadIdx.x;
    const int wid  = tid >> 5;
    const int lane = tid & 31;
    const int g    = lane >> 2;
    const int tg   = lane & 3;
    const int mi   = wid >> 1;           // co-tile 0..3
    const int ni   = wid & 1;            // w-tile 0..1
    const int wrow = (ni * 8 + g) * CIST + 2 * tg;

    // ---- Init A fragments: exact m16n8k16 A layout, hi/lo split. ----
    for (int i = tid; i < AF_U32; i += NTHR) {
        int r = i & 3; int ln = (i >> 2) & 31; int q = (i >> 7) & 3;
        int hl = (i >> 9) & 1; int t = i >> 10; int khkw = t % 9; int mI = t / 9;
        int gg = ln >> 2, tt = ln & 3;
        int co = mI * 16 + gg + ((r & 1) ? 8 : 0);
        int ci = q * 16 + 2 * tt + ((r & 2) ? 8 : 0);
        int kh = khkw / 3, kw = khkw % 3;
        float f0 = Wt[((co * Cc + ci) * 3 + kh) * 3 + kw];
        float f1 = Wt[((co * Cc + ci + 1) * 3 + kh) * 3 + kw];
        __nv_bfloat16 v0, v1;
        if (hl == 0) { v0 = __float2bfloat16(f0); v1 = __float2bfloat16(f1); }
        else {
            __nv_bfloat16 h0 = __float2bfloat16(f0), h1 = __float2bfloat16(f1);
            v0 = __float2bfloat16(f0 - __bfloat162float(h0));
            v1 = __float2bfloat16(f1 - __bfloat162float(h1));
        }
        AFu[i] = (u32)__bfloat16_as_ushort(v0) | ((u32)__bfloat16_as_ushort(v1) << 16);
    }

    const float* Xb = X   + (size_t)b * Cc * Hh * Ww;
    float*       Ob = Out + (size_t)b * Cc * Hh * Ww;

    // ---- Rows 0,1 (unchanged) -> slots 0,1 (bf16 split, incl halo); Out copy. ----
    for (int r = 0; r < 2; r++) {
        for (int i = tid; i < Cc * 18; i += NTHR) {
            int ci = i / 18, wi = i % 18; int w = w0 - 1 + wi;
            float v = (w >= 0 && w < Ww) ? Xb[(ci * Hh + r) * Ww + w] : 0.f;
            split_sts(&BHI[r * SLOT_ELEMS + wi * CIST + ci],
                      &BLO[r * SLOT_ELEMS + wi * CIST + ci], v);
        }
        for (int i = tid; i < Cc * TW; i += NTHR) {
            int ci = i / TW, wq = i % TW;
            Ob[(ci * Hh + r) * Ww + w0 + wq] = Xb[(ci * Hh + r) * Ww + w0 + wq];
        }
    }
    // Zero slot 2 halo cols (edge tiles keep all upd-slot halos 0 forever).
    if (tid < Cc) {
        BHI[2 * SLOT_ELEMS + tid] = __float2bfloat16(0.f);
        BLO[2 * SLOT_ELEMS + tid] = __float2bfloat16(0.f);
        BHI[2 * SLOT_ELEMS + 17 * CIST + tid] = __float2bfloat16(0.f);
        BLO[2 * SLOT_ELEMS + 17 * CIST + tid] = __float2bfloat16(0.f);
    }

    const float bs0 = __ldg(&Bs[mi * 16 + g]);
    const float bs1 = __ldg(&Bs[mi * 16 + g + 8]);

    int* myflag = &g_flags[b * NT + tile];
    int* lflag  = (tile > 0)      ? &g_flags[b * NT + tile - 1] : (int*)0;
    int* rflag  = (tile < NT - 1) ? &g_flags[b * NT + tile + 1] : (int*)0;

    __syncthreads();
    if (tid == 0) { __threadfence(); atomicExch(myflag, 1); }   // rows 0,1 published

    // Prefetch orig row 2.
    float pv[5];
    #pragma unroll
    for (int k = 0; k < 5; k++) {
        int idx = tid + k * NTHR;
        if (idx < Cc * 18) {
            int ci = idx / 18, wi = idx % 18; int w = w0 - 1 + wi;
            pv[k] = (w >= 0 && w < Ww) ? __ldg(&Xb[(ci * Hh + 2) * Ww + w]) : 0.f;
        }
    }

    for (int pos = 2; pos < Hh; pos++) {
        const int OS = 3 + (pos & 1);            // orig slot (pingpong)
        const int US = pos % 3;                  // write slot for updated row pos
        const int S0 = (pos + 1) % 3;            // updated row pos-2
        const int S1 = (pos + 2) % 3;            // updated row pos-1 (halo fresh)

        // Stage orig row pos: bf16 split (full 18 cols) + f32 interior.
        #pragma unroll
        for (int k = 0; k < 5; k++) {
            int idx = tid + k * NTHR;
            if (idx < Cc * 18) {
                int ci = idx / 18, wi = idx % 18;
                split_sts(&BHI[OS * SLOT_ELEMS + wi * CIST + ci],
                          &BLO[OS * SLOT_ELEMS + wi * CIST + ci], pv[k]);
                if (wi >= 1 && wi <= 16)
                    OF[(pos & 1) * Cc * 16 + ci * 16 + (wi - 1)] = pv[k];
            }
        }
        __syncthreads();   // barrier1: orig row staged

        // Prefetch next orig row NOW (full MMA phase to cover the latency).
        if (pos + 1 < Hh) {
            #pragma unroll
            for (int k = 0; k < 5; k++) {
                int idx = tid + k * NTHR;
                if (idx < Cc * 18) {
                    int ci = idx / 18, wi = idx % 18; int w = w0 - 1 + wi;
                    pv[k] = (w >= 0 && w < Ww) ? __ldg(&Xb[(ci * Hh + pos + 1) * Ww + w]) : 0.f;
                }
            }
        }

        // Halo warps: poll neighbor flag, ISSUE the L2 load, let it fly under MMA.
        float hv = 0.f; bool hL = false, hR = false;
        if (tid < Cc && lflag) {
            hL = true;
            while (*(volatile int*)lflag < pos - 1) __nanosleep(32);
            __threadfence();
            hv = __ldcg(&Ob[((size_t)tid * Hh + pos - 1) * Ww + w0 - 1]);
        } else if (tid >= NTHR - Cc && rflag) {
            hR = true;
            int ci = tid - (NTHR - Cc);
            while (*(volatile int*)rflag < pos - 1) __nanosleep(32);
            __threadfence();
            hv = __ldcg(&Ob[((size_t)ci * Hh + pos - 1) * Ww + w0 + TW]);
        }

        // MMA kh=0 (row pos-2) and kh=2 (orig row): independent chains.
        float dA[4] = {0.f, 0.f, 0.f, 0.f};
        float dB[4] = {0.f, 0.f, 0.f, 0.f};
        float dC[4] = {0.f, 0.f, 0.f, 0.f};
        CONV_KH(dA, S0, 0);
        CONV_KH(dC, OS, 2);

        // Store halo (load has had the whole kh0/kh2 window to complete).
        if (hL) split_sts(&BHI[S1 * SLOT_ELEMS + tid], &BLO[S1 * SLOT_ELEMS + tid], hv);
        if (hR) {
            int ci = tid - (NTHR - Cc);
            split_sts(&BHI[S1 * SLOT_ELEMS + 17 * CIST + ci],
                      &BLO[S1 * SLOT_ELEMS + 17 * CIST + ci], hv);
        }
        __syncthreads();   // barrier2: S1 halo in place

        // MMA kh=1 (row pos-1).
        CONV_KH(dB, S1, 1);

        // ---- Epilogue: r = orig + tanh(dA+dB+dC + bias). ----
        const int co0 = mi * 16 + g;
        const int wq  = ni * 8 + 2 * tg;
        const float* ofp = OF + (pos & 1) * Cc * 16;
        float r00 = ofp[co0 * 16 + wq]           + tanhf(dA[0] + dB[0] + dC[0] + bs0);
        float r01 = ofp[co0 * 16 + wq + 1]       + tanhf(dA[1] + dB[1] + dC[1] + bs0);
        float r10 = ofp[(co0 + 8) * 16 + wq]     + tanhf(dA[2] + dB[2] + dC[2] + bs1);
        float r11 = ofp[(co0 + 8) * 16 + wq + 1] + tanhf(dA[3] + dB[3] + dC[3] + bs1);

        float* og = Ob + ((size_t)co0 * Hh + pos) * Ww + w0 + wq;
        *(float2*)og = make_float2(r00, r01);
        *(float2*)(og + 8 * (size_t)Hh * Ww) = make_float2(r10, r11);

        // Updated row -> slot US (interior cols wq+1, wq+2), bf16 split.
        __nv_bfloat16* uh = BHI + US * SLOT_ELEMS;
        __nv_bfloat16* ul = BLO + US * SLOT_ELEMS;
        split_sts(&uh[(wq + 1) * CIST + co0],     &ul[(wq + 1) * CIST + co0],     r00);
        split_sts(&uh[(wq + 2) * CIST + co0],     &ul[(wq + 2) * CIST + co0],     r01);
        split_sts(&uh[(wq + 1) * CIST + co0 + 8], &ul[(wq + 1) * CIST + co0 + 8], r10);
        split_sts(&uh[(wq + 2) * CIST + co0 + 8], &ul[(wq + 2) * CIST + co0 + 8], r11);

        __syncthreads();   // barrier3: row pos stores done (smem + global)
        if (tid == 0) { __threadfence(); atomicExch(myflag, pos); }
    }
}

extern "C" void kernel_launch(void* const* d_in, const int* in_sizes, int n_in,
                              void* d_out, int out_size) {
    const float* X  = (const float*)d_in[0];
    const float* Wt = (const float*)d_in[1];
    const float* Bs = (const float*)d_in[2];
    float* Out = (float*)d_out;
    (void)in_sizes; (void)n_in; (void)out_size;

    cudaFuncSetAttribute(sc_main, cudaFuncAttributeMaxDynamicSharedMemorySize, SMEM_BYTES);

    sc_init_flags<<<1, 128>>>();
    sc_main<<<dim3(NT, Bb), NTHR, SMEM_BYTES>>>(X, Wt, Bs, Out);
}